// round 3
// baseline (speedup 1.0000x reference)
#include <cuda_runtime.h>
#include <math.h>

#define EMBD 1024
#define HEADS 16
#define HD 64
#define BATCH 4
#define SEQ 2048
#define MTOT (BATCH * SEQ)   // 8192
#define NQKV (EMBD + 2 * HD) // 1152

// ---------------- scratch (device globals; no allocation allowed) ----------
__device__ float g_Q[(size_t)MTOT * EMBD];   // Q proj, [B*S, 1024] row-major
__device__ float g_K[(size_t)BATCH * SEQ * HD];
__device__ float g_V[(size_t)BATCH * SEQ * HD];
__device__ float g_A[(size_t)MTOT * EMBD];   // attention output [B*S, 1024]

// ---------------- GEMM tiling ----------------
#define BM 128
#define BN 128
#define BK 16
#define BMP 132   // padded pitch for smem (multiple of 4 -> float4 aligned)
#define BNP 132

// Fused QKV projection: C[8192, 1152] = x @ [Wq | Wk | Wv] + [bq|bk|bv]
__global__ __launch_bounds__(256, 2) void gemm_qkv_kernel(
    const float* __restrict__ x,
    const float* __restrict__ Wq, const float* __restrict__ bq,
    const float* __restrict__ Wk, const float* __restrict__ bk,
    const float* __restrict__ Wv, const float* __restrict__ bv)
{
    __shared__ float As[BK][BMP];
    __shared__ float Bs[BK][BNP];

    const int tid = threadIdx.x;
    const int ty = tid >> 4;        // 0..15
    const int tx = tid & 15;        // 0..15
    const int bm = blockIdx.y * BM;
    const int bn = blockIdx.x * BN;

    // A load mapping: rows ar, ar+64; 4 cols starting at ac4
    const int ar  = tid >> 2;        // 0..63
    const int ac4 = (tid & 3) * 4;   // 0,4,8,12
    // B load mapping: rows br, br+8; 4 cols at bc
    const int br = tid >> 5;         // 0..7
    const int bc = (tid & 31) * 4;   // 0..124

    // resolve weight pointer for this thread's column group (never straddles)
    const int j = bn + bc;
    const float* wp; int col, ldw;
    if (j < EMBD)            { wp = Wq; col = j;             ldw = EMBD; }
    else if (j < EMBD + HD)  { wp = Wk; col = j - EMBD;      ldw = HD; }
    else                     { wp = Wv; col = j - EMBD - HD; ldw = HD; }

    float acc[8][8];
    #pragma unroll
    for (int i = 0; i < 8; i++)
        #pragma unroll
        for (int jj = 0; jj < 8; jj++) acc[i][jj] = 0.0f;

    for (int k0 = 0; k0 < EMBD; k0 += BK) {
        #pragma unroll
        for (int rr = 0; rr < 2; rr++) {
            int row = ar + rr * 64;
            float4 v = *(const float4*)(x + (size_t)(bm + row) * EMBD + k0 + ac4);
            As[ac4 + 0][row] = v.x;
            As[ac4 + 1][row] = v.y;
            As[ac4 + 2][row] = v.z;
            As[ac4 + 3][row] = v.w;
        }
        #pragma unroll
        for (int rr = 0; rr < 2; rr++) {
            int krow = k0 + br + rr * 8;
            float4 v = *(const float4*)(wp + (size_t)krow * ldw + col);
            *(float4*)&Bs[br + rr * 8][bc] = v;
        }
        __syncthreads();

        #pragma unroll
        for (int kk = 0; kk < BK; kk++) {
            float a[8], bfr[8];
            *(float4*)(a)     = *(float4*)&As[kk][ty * 8];
            *(float4*)(a + 4) = *(float4*)&As[kk][ty * 8 + 4];
            *(float4*)(bfr)     = *(float4*)&Bs[kk][tx * 8];
            *(float4*)(bfr + 4) = *(float4*)&Bs[kk][tx * 8 + 4];
            #pragma unroll
            for (int i = 0; i < 8; i++)
                #pragma unroll
                for (int jj = 0; jj < 8; jj++)
                    acc[i][jj] = fmaf(a[i], bfr[jj], acc[i][jj]);
        }
        __syncthreads();
    }

    // epilogue: scatter into Q / K / V
    #pragma unroll
    for (int i = 0; i < 8; i++) {
        int gi = bm + ty * 8 + i;           // 0..8191
        int b  = gi >> 11;                  // /2048
        int s  = gi & (SEQ - 1);
        #pragma unroll
        for (int jj = 0; jj < 8; jj++) {
            int jc = bn + tx * 8 + jj;
            float v = acc[i][jj];
            if (jc < EMBD) {
                g_Q[(size_t)gi * EMBD + jc] = v + bq[jc];
            } else if (jc < EMBD + HD) {
                int d = jc - EMBD;
                g_K[((size_t)b * SEQ + s) * HD + d] = v + bk[d];
            } else {
                int d = jc - EMBD - HD;
                g_V[((size_t)b * SEQ + s) * HD + d] = v + bv[d];
            }
        }
    }
}

// Output projection: out[8192,1024] = g_A @ Wo + bo
__global__ __launch_bounds__(256, 2) void gemm_o_kernel(
    const float* __restrict__ Wo, const float* __restrict__ bo,
    float* __restrict__ out)
{
    __shared__ float As[BK][BMP];
    __shared__ float Bs[BK][BNP];

    const int tid = threadIdx.x;
    const int ty = tid >> 4;
    const int tx = tid & 15;
    const int bm = blockIdx.y * BM;
    const int bn = blockIdx.x * BN;

    const int ar  = tid >> 2;
    const int ac4 = (tid & 3) * 4;
    const int br = tid >> 5;
    const int bc = (tid & 31) * 4;

    float acc[8][8];
    #pragma unroll
    for (int i = 0; i < 8; i++)
        #pragma unroll
        for (int jj = 0; jj < 8; jj++) acc[i][jj] = 0.0f;

    for (int k0 = 0; k0 < EMBD; k0 += BK) {
        #pragma unroll
        for (int rr = 0; rr < 2; rr++) {
            int row = ar + rr * 64;
            float4 v = *(const float4*)(g_A + (size_t)(bm + row) * EMBD + k0 + ac4);
            As[ac4 + 0][row] = v.x;
            As[ac4 + 1][row] = v.y;
            As[ac4 + 2][row] = v.z;
            As[ac4 + 3][row] = v.w;
        }
        #pragma unroll
        for (int rr = 0; rr < 2; rr++) {
            int krow = k0 + br + rr * 8;
            float4 v = *(const float4*)(Wo + (size_t)krow * EMBD + bn + bc);
            *(float4*)&Bs[br + rr * 8][bc] = v;
        }
        __syncthreads();

        #pragma unroll
        for (int kk = 0; kk < BK; kk++) {
            float a[8], bfr[8];
            *(float4*)(a)     = *(float4*)&As[kk][ty * 8];
            *(float4*)(a + 4) = *(float4*)&As[kk][ty * 8 + 4];
            *(float4*)(bfr)     = *(float4*)&Bs[kk][tx * 8];
            *(float4*)(bfr + 4) = *(float4*)&Bs[kk][tx * 8 + 4];
            #pragma unroll
            for (int i = 0; i < 8; i++)
                #pragma unroll
                for (int jj = 0; jj < 8; jj++)
                    acc[i][jj] = fmaf(a[i], bfr[jj], acc[i][jj]);
        }
        __syncthreads();
    }

    #pragma unroll
    for (int i = 0; i < 8; i++) {
        int gi = bm + ty * 8 + i;
        float* orow = out + (size_t)gi * EMBD + bn + tx * 8;
        const float* bop = bo + bn + tx * 8;
        float4 o0 = make_float4(acc[i][0] + bop[0], acc[i][1] + bop[1],
                                acc[i][2] + bop[2], acc[i][3] + bop[3]);
        float4 o1 = make_float4(acc[i][4] + bop[4], acc[i][5] + bop[5],
                                acc[i][6] + bop[6], acc[i][7] + bop[7]);
        *(float4*)(orow)     = o0;
        *(float4*)(orow + 4) = o1;
    }
}

// ---------------- flash attention (fp32, online softmax) ----------------
#define QT 128
#define KT 64
#define QTP 132
#define KDP 68
// dynamic smem floats: Qs[64][QTP] + Ks[64][KDP] + Vs[KT][KDP] + Ps[QT][KDP]
#define ATTN_SMEM_FLOATS (64 * QTP + 64 * KDP + KT * KDP + QT * KDP)
#define ATTN_SMEM_BYTES (ATTN_SMEM_FLOATS * 4)

__global__ __launch_bounds__(256, 2) void attn_kernel()
{
    extern __shared__ float sm[];
    float* Qs = sm;                       // Qs[d][r]  (transposed, scaled)
    float* Ks = Qs + 64 * QTP;            // Ks[d][t]  (transposed)
    float* Vs = Ks + 64 * KDP;            // Vs[t][d]
    float* Ps = Vs + KT * KDP;            // Ps[row][key] row-major, pitch KDP

    const int tid = threadIdx.x;
    const int ty = tid >> 4;              // 0..15
    const int tx = tid & 15;              // 0..15
    const int q0 = blockIdx.x * QT;
    const int h  = blockIdx.y;
    const int b  = blockIdx.z;

    const float* Qg = g_Q + ((size_t)(b * SEQ + q0)) * EMBD + h * HD;
    const float* Kg = g_K + (size_t)b * SEQ * HD;
    const float* Vg = g_V + (size_t)b * SEQ * HD;
    const float scale = 0.125f;           // 1/sqrt(64)

    // load Q tile, transpose, fold scale in
    #pragma unroll
    for (int rep = 0; rep < 8; rep++) {
        int idx = tid + rep * 256;        // 0..2047
        int r   = idx >> 4;               // 0..127
        int c4  = (idx & 15) * 4;
        float4 v = *(const float4*)(Qg + (size_t)r * EMBD + c4);
        Qs[(c4 + 0) * QTP + r] = v.x * scale;
        Qs[(c4 + 1) * QTP + r] = v.y * scale;
        Qs[(c4 + 2) * QTP + r] = v.z * scale;
        Qs[(c4 + 3) * QTP + r] = v.w * scale;
    }

    float m_prev[8], l_acc[8], o[8][4];
    #pragma unroll
    for (int i = 0; i < 8; i++) {
        m_prev[i] = -INFINITY;
        l_acc[i] = 0.0f;
        #pragma unroll
        for (int c = 0; c < 4; c++) o[i][c] = 0.0f;
    }

    for (int t0 = 0; t0 < SEQ; t0 += KT) {
        __syncthreads();   // prior iteration finished reading Ks/Vs/Ps
        #pragma unroll
        for (int rep = 0; rep < 4; rep++) {
            int idx = tid + rep * 256;    // 0..1023
            int r   = idx >> 4;           // 0..63
            int c4  = (idx & 15) * 4;
            float4 kv = *(const float4*)(Kg + (size_t)(t0 + r) * HD + c4);
            Ks[(c4 + 0) * KDP + r] = kv.x;
            Ks[(c4 + 1) * KDP + r] = kv.y;
            Ks[(c4 + 2) * KDP + r] = kv.z;
            Ks[(c4 + 3) * KDP + r] = kv.w;
            float4 vv = *(const float4*)(Vg + (size_t)(t0 + r) * HD + c4);
            *(float4*)&Vs[r * KDP + c4] = vv;
        }
        __syncthreads();

        // S = (scaled Q) @ K^T  : per-thread 8 rows x 4 keys
        float s[8][4];
        #pragma unroll
        for (int i = 0; i < 8; i++)
            #pragma unroll
            for (int c = 0; c < 4; c++) s[i][c] = 0.0f;

        #pragma unroll
        for (int d = 0; d < 64; d++) {
            float a[8], bf[4];
            *(float4*)(a)     = *(float4*)&Qs[d * QTP + ty * 8];
            *(float4*)(a + 4) = *(float4*)&Qs[d * QTP + ty * 8 + 4];
            *(float4*)(bf)    = *(float4*)&Ks[d * KDP + tx * 4];
            #pragma unroll
            for (int i = 0; i < 8; i++)
                #pragma unroll
                for (int c = 0; c < 4; c++)
                    s[i][c] = fmaf(a[i], bf[c], s[i][c]);
        }

        // online softmax; row owned by 16 lanes sharing ty
        #pragma unroll
        for (int i = 0; i < 8; i++) {
            float mloc = fmaxf(fmaxf(s[i][0], s[i][1]), fmaxf(s[i][2], s[i][3]));
            #pragma unroll
            for (int off = 1; off < 16; off <<= 1)
                mloc = fmaxf(mloc, __shfl_xor_sync(0xffffffffu, mloc, off));
            float mnew = fmaxf(m_prev[i], mloc);
            float corr = __expf(m_prev[i] - mnew);
            float p[4], lsum = 0.0f;
            #pragma unroll
            for (int c = 0; c < 4; c++) {
                p[c] = __expf(s[i][c] - mnew);
                lsum += p[c];
            }
            #pragma unroll
            for (int off = 1; off < 16; off <<= 1)
                lsum += __shfl_xor_sync(0xffffffffu, lsum, off);
            l_acc[i] = l_acc[i] * corr + lsum;
            m_prev[i] = mnew;
            #pragma unroll
            for (int c = 0; c < 4; c++) o[i][c] *= corr;
            // store P row-major: Ps[row][key], one STS.128 per row
            *(float4*)&Ps[(ty * 8 + i) * KDP + tx * 4] =
                make_float4(p[0], p[1], p[2], p[3]);
        }
        __syncthreads();

        // O += P @ V : per-thread 8 rows x 4 dims (dims = tx*4..)
        #pragma unroll
        for (int k = 0; k < KT; k++) {
            float bf[4];
            *(float4*)(bf) = *(float4*)&Vs[k * KDP + tx * 4];
            #pragma unroll
            for (int i = 0; i < 8; i++) {
                float a = Ps[(ty * 8 + i) * KDP + k];   // broadcast across tx
                #pragma unroll
                for (int c = 0; c < 4; c++)
                    o[i][c] = fmaf(a, bf[c], o[i][c]);
            }
        }
    }

    // normalize and write to g_A[b, q, h*64 + d]
    #pragma unroll
    for (int i = 0; i < 8; i++) {
        int q = q0 + ty * 8 + i;
        float inv = 1.0f / l_acc[i];
        float4 vout = make_float4(o[i][0] * inv, o[i][1] * inv,
                                  o[i][2] * inv, o[i][3] * inv);
        *(float4*)(g_A + ((size_t)(b * SEQ + q)) * EMBD + h * HD + tx * 4) = vout;
    }
}

// ---------------- launch ----------------
extern "C" void kernel_launch(void* const* d_in, const int* in_sizes, int n_in,
                              void* d_out, int out_size)
{
    const float* x  = (const float*)d_in[0];
    const float* Wq = (const float*)d_in[1];
    const float* bq = (const float*)d_in[2];
    const float* Wk = (const float*)d_in[3];
    const float* bk = (const float*)d_in[4];
    const float* Wv = (const float*)d_in[5];
    const float* bv = (const float*)d_in[6];
    const float* Wo = (const float*)d_in[7];
    const float* bo = (const float*)d_in[8];
    float* out = (float*)d_out;

    cudaFuncSetAttribute(attn_kernel, cudaFuncAttributeMaxDynamicSharedMemorySize,
                         ATTN_SMEM_BYTES);

    gemm_qkv_kernel<<<dim3(NQKV / BN, MTOT / BM), 256>>>(x, Wq, bq, Wk, bk, Wv, bv);
    attn_kernel<<<dim3(SEQ / QT, HEADS, BATCH), 256, ATTN_SMEM_BYTES>>>();
    gemm_o_kernel<<<dim3(EMBD / BN, MTOT / BM), 256>>>(Wo, bo, out);
}

// round 5
// speedup vs baseline: 1.6507x; 1.6507x over previous
#include <cuda_runtime.h>
#include <math.h>
#include <stdint.h>

#define EMBD 1024
#define HEADS 16
#define HD 64
#define BATCH 4
#define SEQ 2048
#define MTOT (BATCH * SEQ)   // 8192
#define NQKV (EMBD + 2 * HD) // 1152

// ---------------- scratch (device globals; no allocation allowed) ----------
__device__ float g_Q[(size_t)MTOT * EMBD];   // Q proj (tf32-rounded), [B*S, 1024]
__device__ float g_K[(size_t)BATCH * SEQ * HD];  // tf32-rounded
__device__ float g_V[(size_t)BATCH * SEQ * HD];  // tf32-rounded
__device__ float g_A[(size_t)MTOT * EMBD];   // attention output [B*S, 1024]

// ---------------- helpers ----------------
__device__ __forceinline__ float to_tf32(float x) {
    uint32_t u;
    asm("cvt.rna.tf32.f32 %0, %1;" : "=r"(u) : "f"(x));
    return __uint_as_float(u);
}

__device__ __forceinline__ void mma_tf32(float acc[4], const uint32_t a[4],
                                         uint32_t b0, uint32_t b1) {
    asm volatile(
        "mma.sync.aligned.m16n8k8.row.col.f32.tf32.tf32.f32 "
        "{%0,%1,%2,%3}, {%4,%5,%6,%7}, {%8,%9}, {%0,%1,%2,%3};"
        : "+f"(acc[0]), "+f"(acc[1]), "+f"(acc[2]), "+f"(acc[3])
        : "r"(a[0]), "r"(a[1]), "r"(a[2]), "r"(a[3]), "r"(b0), "r"(b1));
}

// exp on the FMA pipe (no MUFU): valid for x <= 0 (and x = -inf -> ~0)
__device__ __forceinline__ float fast_exp(float x) {
    float t = x * 1.4426950408889634f;
    t = fmaxf(t, -126.0f);
    float z = t + 12582912.0f;               // round-to-nearest-int magic
    int  n = __float_as_int(z) - 0x4B400000;
    float r = t - (z - 12582912.0f);         // r in [-0.5, 0.5]
    float p = 1.3333558146e-3f;
    p = fmaf(p, r, 9.6181291076e-3f);
    p = fmaf(p, r, 5.5504108665e-2f);
    p = fmaf(p, r, 2.4022650696e-1f);
    p = fmaf(p, r, 6.9314718056e-1f);
    p = fmaf(p, r, 1.0f);
    return p * __int_as_float((n + 127) << 23);
}

__device__ __forceinline__ float trunc_tf32(float x) {
    return __uint_as_float(__float_as_uint(x) & 0xFFFFE000u);
}

// ---------------- GEMM tiling (fp32 projections) ----------------
#define BM 128
#define BN 128
#define BK 16
#define BMP 132
#define BNP 132

// Fused QKV projection: C[8192, 1152] = x @ [Wq | Wk | Wv] + [bq|bk|bv]
// Epilogue rounds Q/K/V to tf32 (rna) so the attention kernel consumes
// tensor-core-ready operands with no per-tile cvt cost.
__global__ __launch_bounds__(256, 2) void gemm_qkv_kernel(
    const float* __restrict__ x,
    const float* __restrict__ Wq, const float* __restrict__ bq,
    const float* __restrict__ Wk, const float* __restrict__ bk,
    const float* __restrict__ Wv, const float* __restrict__ bv)
{
    __shared__ float As[BK][BMP];
    __shared__ float Bs[BK][BNP];

    const int tid = threadIdx.x;
    const int ty = tid >> 4;
    const int tx = tid & 15;
    const int bm = blockIdx.y * BM;
    const int bn = blockIdx.x * BN;

    const int ar  = tid >> 2;
    const int ac4 = (tid & 3) * 4;
    const int br = tid >> 5;
    const int bc = (tid & 31) * 4;

    const int j = bn + bc;
    const float* wp; int col, ldw;
    if (j < EMBD)            { wp = Wq; col = j;             ldw = EMBD; }
    else if (j < EMBD + HD)  { wp = Wk; col = j - EMBD;      ldw = HD; }
    else                     { wp = Wv; col = j - EMBD - HD; ldw = HD; }

    float acc[8][8];
    #pragma unroll
    for (int i = 0; i < 8; i++)
        #pragma unroll
        for (int jj = 0; jj < 8; jj++) acc[i][jj] = 0.0f;

    for (int k0 = 0; k0 < EMBD; k0 += BK) {
        #pragma unroll
        for (int rr = 0; rr < 2; rr++) {
            int row = ar + rr * 64;
            float4 v = *(const float4*)(x + (size_t)(bm + row) * EMBD + k0 + ac4);
            As[ac4 + 0][row] = v.x;
            As[ac4 + 1][row] = v.y;
            As[ac4 + 2][row] = v.z;
            As[ac4 + 3][row] = v.w;
        }
        #pragma unroll
        for (int rr = 0; rr < 2; rr++) {
            int krow = k0 + br + rr * 8;
            float4 v = *(const float4*)(wp + (size_t)krow * ldw + col);
            *(float4*)&Bs[br + rr * 8][bc] = v;
        }
        __syncthreads();

        #pragma unroll
        for (int kk = 0; kk < BK; kk++) {
            float a[8], bfr[8];
            *(float4*)(a)     = *(float4*)&As[kk][ty * 8];
            *(float4*)(a + 4) = *(float4*)&As[kk][ty * 8 + 4];
            *(float4*)(bfr)     = *(float4*)&Bs[kk][tx * 8];
            *(float4*)(bfr + 4) = *(float4*)&Bs[kk][tx * 8 + 4];
            #pragma unroll
            for (int i = 0; i < 8; i++)
                #pragma unroll
                for (int jj = 0; jj < 8; jj++)
                    acc[i][jj] = fmaf(a[i], bfr[jj], acc[i][jj]);
        }
        __syncthreads();
    }

    #pragma unroll
    for (int i = 0; i < 8; i++) {
        int gi = bm + ty * 8 + i;
        int b  = gi >> 11;
        int s  = gi & (SEQ - 1);
        #pragma unroll
        for (int jj = 0; jj < 8; jj++) {
            int jc = bn + tx * 8 + jj;
            float v = acc[i][jj];
            if (jc < EMBD) {
                g_Q[(size_t)gi * EMBD + jc] = to_tf32(v + bq[jc]);
            } else if (jc < EMBD + HD) {
                int d = jc - EMBD;
                g_K[((size_t)b * SEQ + s) * HD + d] = to_tf32(v + bk[d]);
            } else {
                int d = jc - EMBD - HD;
                g_V[((size_t)b * SEQ + s) * HD + d] = to_tf32(v + bv[d]);
            }
        }
    }
}

// Output projection: out[8192,1024] = g_A @ Wo + bo  (fp32)
__global__ __launch_bounds__(256, 2) void gemm_o_kernel(
    const float* __restrict__ Wo, const float* __restrict__ bo,
    float* __restrict__ out)
{
    __shared__ float As[BK][BMP];
    __shared__ float Bs[BK][BNP];

    const int tid = threadIdx.x;
    const int ty = tid >> 4;
    const int tx = tid & 15;
    const int bm = blockIdx.y * BM;
    const int bn = blockIdx.x * BN;

    const int ar  = tid >> 2;
    const int ac4 = (tid & 3) * 4;
    const int br = tid >> 5;
    const int bc = (tid & 31) * 4;

    float acc[8][8];
    #pragma unroll
    for (int i = 0; i < 8; i++)
        #pragma unroll
        for (int jj = 0; jj < 8; jj++) acc[i][jj] = 0.0f;

    for (int k0 = 0; k0 < EMBD; k0 += BK) {
        #pragma unroll
        for (int rr = 0; rr < 2; rr++) {
            int row = ar + rr * 64;
            float4 v = *(const float4*)(g_A + (size_t)(bm + row) * EMBD + k0 + ac4);
            As[ac4 + 0][row] = v.x;
            As[ac4 + 1][row] = v.y;
            As[ac4 + 2][row] = v.z;
            As[ac4 + 3][row] = v.w;
        }
        #pragma unroll
        for (int rr = 0; rr < 2; rr++) {
            int krow = k0 + br + rr * 8;
            float4 v = *(const float4*)(Wo + (size_t)krow * EMBD + bn + bc);
            *(float4*)&Bs[br + rr * 8][bc] = v;
        }
        __syncthreads();

        #pragma unroll
        for (int kk = 0; kk < BK; kk++) {
            float a[8], bfr[8];
            *(float4*)(a)     = *(float4*)&As[kk][ty * 8];
            *(float4*)(a + 4) = *(float4*)&As[kk][ty * 8 + 4];
            *(float4*)(bfr)     = *(float4*)&Bs[kk][tx * 8];
            *(float4*)(bfr + 4) = *(float4*)&Bs[kk][tx * 8 + 4];
            #pragma unroll
            for (int i = 0; i < 8; i++)
                #pragma unroll
                for (int jj = 0; jj < 8; jj++)
                    acc[i][jj] = fmaf(a[i], bfr[jj], acc[i][jj]);
        }
        __syncthreads();
    }

    #pragma unroll
    for (int i = 0; i < 8; i++) {
        int gi = bm + ty * 8 + i;
        float* orow = out + (size_t)gi * EMBD + bn + tx * 8;
        const float* bop = bo + bn + tx * 8;
        float4 o0 = make_float4(acc[i][0] + bop[0], acc[i][1] + bop[1],
                                acc[i][2] + bop[2], acc[i][3] + bop[3]);
        float4 o1 = make_float4(acc[i][4] + bop[4], acc[i][5] + bop[5],
                                acc[i][6] + bop[6], acc[i][7] + bop[7]);
        *(float4*)(orow)     = o0;
        *(float4*)(orow + 4) = o1;
    }
}

// ---------------- flash attention (tf32 mma.sync, online softmax) --------
// CTA: 128 q-rows, 8 warps, each warp owns 16 rows (one m16 fragment row).
// Key tile = 64. Q fragments persist in registers for the whole kernel.
#define QT 128
#define KT2 64
#define KP 68    // Ks pitch  (bank-conflict-free for S-mma B loads)
#define VP 72    // Vs pitch  (bank-conflict-free for PV-mma B loads)
#define PP 68    // Ps pitch  (bank-conflict-free for PV-mma A loads)
// smem: Ks[64][68] + Vs[64][72] + Ps[128][68]  (Ps doubles as Q staging)
#define ATTN_SMEM_FLOATS (KT2 * KP + KT2 * VP + QT * PP)
#define ATTN_SMEM_BYTES (ATTN_SMEM_FLOATS * 4)

__global__ __launch_bounds__(256, 1) void attn_kernel()
{
    extern __shared__ float sm[];
    float* Ks = sm;                  // [key][d]
    float* Vs = Ks + KT2 * KP;       // [key][d]
    float* Ps = Vs + KT2 * VP;       // [row][key] ; Q staging before loop

    const int tid  = threadIdx.x;
    const int warp = tid >> 5;
    const int lane = tid & 31;
    const int gr   = lane >> 2;      // groupID 0..7
    const int gc   = lane & 3;       // thread-in-group 0..3
    const int q0 = blockIdx.x * QT;
    const int h  = blockIdx.y;
    const int b  = blockIdx.z;

    const float* Qg = g_Q + ((size_t)(b * SEQ + q0)) * EMBD + h * HD;
    const float* Kg = g_K + (size_t)b * SEQ * HD;
    const float* Vg = g_V + (size_t)b * SEQ * HD;

    // ---- stage Q tile into Ps (scaled by 1/8 = exact on tf32 values) ----
    #pragma unroll
    for (int rep = 0; rep < 8; rep++) {
        int idx = tid + rep * 256;            // 0..2047
        int r   = idx >> 4;                   // 0..127
        int c4  = (idx & 15) * 4;
        float4 v = *(const float4*)(Qg + (size_t)r * EMBD + c4);
        v.x *= 0.125f; v.y *= 0.125f; v.z *= 0.125f; v.w *= 0.125f;
        *(float4*)&Ps[r * PP + c4] = v;
    }
    __syncthreads();

    // ---- load persistent Q fragments: A of m16n8k8, 8 k-steps ----
    const int r0 = warp * 16 + gr;            // warp-local row (CTA index)
    uint32_t qf[8][4];
    #pragma unroll
    for (int k = 0; k < 8; k++) {
        qf[k][0] = __float_as_uint(Ps[r0 * PP + k * 8 + gc]);
        qf[k][1] = __float_as_uint(Ps[(r0 + 8) * PP + k * 8 + gc]);
        qf[k][2] = __float_as_uint(Ps[r0 * PP + k * 8 + gc + 4]);
        qf[k][3] = __float_as_uint(Ps[(r0 + 8) * PP + k * 8 + gc + 4]);
    }

    float oacc[8][4];
    #pragma unroll
    for (int n = 0; n < 8; n++)
        #pragma unroll
        for (int c = 0; c < 4; c++) oacc[n][c] = 0.0f;
    float m0 = -INFINITY, m1 = -INFINITY, l0 = 0.0f, l1 = 0.0f;

    for (int t0 = 0; t0 < SEQ; t0 += KT2) {
        __syncthreads();  // all warps done reading Ks/Vs of prior tile
        #pragma unroll
        for (int rep = 0; rep < 4; rep++) {
            int idx = tid + rep * 256;        // 0..1023
            int r   = idx >> 4;               // 0..63
            int c4  = (idx & 15) * 4;
            float4 kv = *(const float4*)(Kg + (size_t)(t0 + r) * HD + c4);
            *(float4*)&Ks[r * KP + c4] = kv;
            float4 vv = *(const float4*)(Vg + (size_t)(t0 + r) * HD + c4);
            *(float4*)&Vs[r * VP + c4] = vv;
        }
        __syncthreads();

        // ---- S = Qs @ K^T : 8 n-tiles (8 keys each) x 8 k-steps ----
        float sacc[8][4];
        #pragma unroll
        for (int n = 0; n < 8; n++)
            #pragma unroll
            for (int c = 0; c < 4; c++) sacc[n][c] = 0.0f;

        #pragma unroll
        for (int n = 0; n < 8; n++) {
            const float* krow = &Ks[(n * 8 + gr) * KP + gc];
            #pragma unroll
            for (int k = 0; k < 8; k++) {
                uint32_t b0 = __float_as_uint(krow[k * 8]);
                uint32_t b1 = __float_as_uint(krow[k * 8 + 4]);
                mma_tf32(sacc[n], qf[k], b0, b1);
            }
        }

        // ---- online softmax (rows r0 and r0+8) ----
        float rm0 = -INFINITY, rm1 = -INFINITY;
        #pragma unroll
        for (int n = 0; n < 8; n++) {
            rm0 = fmaxf(rm0, fmaxf(sacc[n][0], sacc[n][1]));
            rm1 = fmaxf(rm1, fmaxf(sacc[n][2], sacc[n][3]));
        }
        rm0 = fmaxf(rm0, __shfl_xor_sync(0xffffffffu, rm0, 1));
        rm0 = fmaxf(rm0, __shfl_xor_sync(0xffffffffu, rm0, 2));
        rm1 = fmaxf(rm1, __shfl_xor_sync(0xffffffffu, rm1, 1));
        rm1 = fmaxf(rm1, __shfl_xor_sync(0xffffffffu, rm1, 2));
        float mn0 = fmaxf(m0, rm0), mn1 = fmaxf(m1, rm1);
        float corr0 = fast_exp(m0 - mn0), corr1 = fast_exp(m1 - mn1);
        m0 = mn0; m1 = mn1;

        float ls0 = 0.0f, ls1 = 0.0f;
        #pragma unroll
        for (int n = 0; n < 8; n++) {
            float t00 = trunc_tf32(fast_exp(sacc[n][0] - m0));
            float t01 = trunc_tf32(fast_exp(sacc[n][1] - m0));
            float t10 = trunc_tf32(fast_exp(sacc[n][2] - m1));
            float t11 = trunc_tf32(fast_exp(sacc[n][3] - m1));
            ls0 += t00 + t01;
            ls1 += t10 + t11;
            int col = n * 8 + 2 * gc;
            *(float2*)&Ps[r0 * PP + col]       = make_float2(t00, t01);
            *(float2*)&Ps[(r0 + 8) * PP + col] = make_float2(t10, t11);
        }
        ls0 += __shfl_xor_sync(0xffffffffu, ls0, 1);
        ls0 += __shfl_xor_sync(0xffffffffu, ls0, 2);
        ls1 += __shfl_xor_sync(0xffffffffu, ls1, 1);
        ls1 += __shfl_xor_sync(0xffffffffu, ls1, 2);
        l0 = l0 * corr0 + ls0;
        l1 = l1 * corr1 + ls1;

        #pragma unroll
        for (int n = 0; n < 8; n++) {
            oacc[n][0] *= corr0; oacc[n][1] *= corr0;
            oacc[n][2] *= corr1; oacc[n][3] *= corr1;
        }
        __syncwarp();   // P visible to all lanes of this warp

        // ---- O += P @ V : 8 k-steps (keys) x 8 n-tiles (d) ----
        #pragma unroll
        for (int k = 0; k < 8; k++) {
            uint32_t a[4];
            a[0] = __float_as_uint(Ps[r0 * PP + k * 8 + gc]);
            a[1] = __float_as_uint(Ps[(r0 + 8) * PP + k * 8 + gc]);
            a[2] = __float_as_uint(Ps[r0 * PP + k * 8 + gc + 4]);
            a[3] = __float_as_uint(Ps[(r0 + 8) * PP + k * 8 + gc + 4]);
            #pragma unroll
            for (int n = 0; n < 8; n++) {
                uint32_t b0 = __float_as_uint(Vs[(k * 8 + gc) * VP + n * 8 + gr]);
                uint32_t b1 = __float_as_uint(Vs[(k * 8 + gc + 4) * VP + n * 8 + gr]);
                mma_tf32(oacc[n], a, b0, b1);
            }
        }
    }

    // ---- normalize & write g_A[b, q, h*64 + d] ----
    float inv0 = 1.0f / l0, inv1 = 1.0f / l1;
    #pragma unroll
    for (int n = 0; n < 8; n++) {
        int col = h * HD + n * 8 + 2 * gc;
        size_t base0 = ((size_t)(b * SEQ + q0 + r0)) * EMBD + col;
        size_t base1 = ((size_t)(b * SEQ + q0 + r0 + 8)) * EMBD + col;
        *(float2*)&g_A[base0] = make_float2(oacc[n][0] * inv0, oacc[n][1] * inv0);
        *(float2*)&g_A[base1] = make_float2(oacc[n][2] * inv1, oacc[n][3] * inv1);
    }
}

// ---------------- launch ----------------
extern "C" void kernel_launch(void* const* d_in, const int* in_sizes, int n_in,
                              void* d_out, int out_size)
{
    const float* x  = (const float*)d_in[0];
    const float* Wq = (const float*)d_in[1];
    const float* bq = (const float*)d_in[2];
    const float* Wk = (const float*)d_in[3];
    const float* bk = (const float*)d_in[4];
    const float* Wv = (const float*)d_in[5];
    const float* bv = (const float*)d_in[6];
    const float* Wo = (const float*)d_in[7];
    const float* bo = (const float*)d_in[8];
    float* out = (float*)d_out;

    cudaFuncSetAttribute(attn_kernel, cudaFuncAttributeMaxDynamicSharedMemorySize,
                         ATTN_SMEM_BYTES);

    gemm_qkv_kernel<<<dim3(NQKV / BN, MTOT / BM), 256>>>(x, Wq, bq, Wk, bk, Wv, bv);
    attn_kernel<<<dim3(SEQ / QT, HEADS, BATCH), 256, ATTN_SMEM_BYTES>>>();
    gemm_o_kernel<<<dim3(EMBD / BN, MTOT / BM), 256>>>(Wo, bo, out);
}

// round 6
// speedup vs baseline: 2.4853x; 1.5056x over previous
#include <cuda_runtime.h>
#include <math.h>
#include <stdint.h>

#define EMBD 1024
#define HEADS 16
#define HD 64
#define BATCH 4
#define SEQ 2048
#define MTOT (BATCH * SEQ)   // 8192
#define NQKV (EMBD + 2 * HD) // 1152

// ---------------- scratch (device globals; no allocation allowed) ----------
__device__ float g_Q[(size_t)MTOT * EMBD];   // Q proj (tf32-rounded), [B*S, 1024]
__device__ float g_K[(size_t)BATCH * SEQ * HD];  // tf32-rounded
__device__ float g_V[(size_t)BATCH * SEQ * HD];  // tf32-rounded
__device__ float g_A[(size_t)MTOT * EMBD];   // attention output [B*S, 1024]

// ---------------- helpers ----------------
__device__ __forceinline__ float to_tf32(float x) {
    uint32_t u;
    asm("cvt.rna.tf32.f32 %0, %1;" : "=r"(u) : "f"(x));
    return __uint_as_float(u);
}

__device__ __forceinline__ float4 to_tf32_4(float4 v) {
    return make_float4(to_tf32(v.x), to_tf32(v.y), to_tf32(v.z), to_tf32(v.w));
}

__device__ __forceinline__ void mma_tf32(float acc[4], const uint32_t a[4],
                                         uint32_t b0, uint32_t b1) {
    asm volatile(
        "mma.sync.aligned.m16n8k8.row.col.f32.tf32.tf32.f32 "
        "{%0,%1,%2,%3}, {%4,%5,%6,%7}, {%8,%9}, {%0,%1,%2,%3};"
        : "+f"(acc[0]), "+f"(acc[1]), "+f"(acc[2]), "+f"(acc[3])
        : "r"(a[0]), "r"(a[1]), "r"(a[2]), "r"(a[3]), "r"(b0), "r"(b1));
}

// exp on the FMA pipe (no MUFU): valid for x <= 0 (and x = -inf -> ~0)
__device__ __forceinline__ float fast_exp(float x) {
    float t = x * 1.4426950408889634f;
    t = fmaxf(t, -126.0f);
    float z = t + 12582912.0f;               // round-to-nearest-int magic
    int  n = __float_as_int(z) - 0x4B400000;
    float r = t - (z - 12582912.0f);         // r in [-0.5, 0.5]
    float p = 1.3333558146e-3f;
    p = fmaf(p, r, 9.6181291076e-3f);
    p = fmaf(p, r, 5.5504108665e-2f);
    p = fmaf(p, r, 2.4022650696e-1f);
    p = fmaf(p, r, 6.9314718056e-1f);
    p = fmaf(p, r, 1.0f);
    return p * __int_as_float((n + 127) << 23);
}

__device__ __forceinline__ float trunc_tf32(float x) {
    return __uint_as_float(__float_as_uint(x) & 0xFFFFE000u);
}

// ---------------- tf32 tensor-core projection GEMMs ----------------
// CTA 128x128, BK=32, 8 warps (2x4), warp tile 64x32 (4x4 m16n8k8 accs).
#define TBK 32
#define AP 36    // As pitch: fragment loads bank-conflict-free (gr*4+gc)
#define BP 132   // Bs pitch: fragment loads bank-conflict-free (gc*4+gr+8nt)

// Fused QKV projection: [8192,1152] = x @ [Wq|Wk|Wv] + [bq|bk|bv], tf32 mma.
__global__ __launch_bounds__(256, 1) void gemm_qkv_kernel(
    const float* __restrict__ x,
    const float* __restrict__ Wq, const float* __restrict__ bq,
    const float* __restrict__ Wk, const float* __restrict__ bk,
    const float* __restrict__ Wv, const float* __restrict__ bv)
{
    __shared__ float As[128][AP];   // [row][k], tf32-rounded
    __shared__ float Bs[TBK][BP];   // [k][col], tf32-rounded

    const int tid  = threadIdx.x;
    const int warp = tid >> 5;
    const int lane = tid & 31;
    const int gr   = lane >> 2;     // 0..7
    const int gc   = lane & 3;      // 0..3
    const int wm   = warp >> 2;     // 0..1
    const int wn   = warp & 3;      // 0..3
    const int bm   = blockIdx.y * 128;
    const int bn   = blockIdx.x * 128;

    // A load map: 4 reps, row=idx>>3, kcol=(idx&7)*4
    const int arow = tid >> 3;            // base row for rep0 (0..31)
    const int ac   = (tid & 7) * 4;       // 0..28
    // B load map: 4 reps, row=tid>>5 + rep*8, col=(tid&31)*4 (fixed)
    const int brow = tid >> 5;            // 0..7
    const int bcol = (tid & 31) * 4;      // 0..124

    // weight pointer select (column group never straddles Q/K/V boundaries)
    const int j = bn + bcol;
    const float* wp; int wcol, ldw;
    if (j < EMBD)            { wp = Wq; wcol = j;             ldw = EMBD; }
    else if (j < EMBD + HD)  { wp = Wk; wcol = j - EMBD;      ldw = HD; }
    else                     { wp = Wv; wcol = j - EMBD - HD; ldw = HD; }

    float acc[4][4][4];
    #pragma unroll
    for (int mt = 0; mt < 4; mt++)
        #pragma unroll
        for (int nt = 0; nt < 4; nt++)
            #pragma unroll
            for (int c = 0; c < 4; c++) acc[mt][nt][c] = 0.0f;

    float4 pa[4], pb[4];
    // prologue: tile 0
    #pragma unroll
    for (int rep = 0; rep < 4; rep++) {
        pa[rep] = *(const float4*)(x + (size_t)(bm + arow + rep * 32) * EMBD + ac);
        pb[rep] = *(const float4*)(wp + (size_t)(brow + rep * 8) * ldw + wcol);
    }
    #pragma unroll
    for (int rep = 0; rep < 4; rep++) {
        *(float4*)&As[arow + rep * 32][ac] = to_tf32_4(pa[rep]);
        *(float4*)&Bs[brow + rep * 8][bcol] = to_tf32_4(pb[rep]);
    }
    __syncthreads();

    for (int k0 = TBK; k0 <= EMBD; k0 += TBK) {
        if (k0 < EMBD) {
            #pragma unroll
            for (int rep = 0; rep < 4; rep++) {
                pa[rep] = *(const float4*)(x + (size_t)(bm + arow + rep * 32) * EMBD + k0 + ac);
                pb[rep] = *(const float4*)(wp + (size_t)(k0 + brow + rep * 8) * ldw + wcol);
            }
        }
        #pragma unroll
        for (int k8 = 0; k8 < 4; k8++) {
            uint32_t af[4][4];
            #pragma unroll
            for (int mt = 0; mt < 4; mt++) {
                int r = wm * 64 + mt * 16 + gr;
                int c = k8 * 8 + gc;
                af[mt][0] = __float_as_uint(As[r][c]);
                af[mt][1] = __float_as_uint(As[r + 8][c]);
                af[mt][2] = __float_as_uint(As[r][c + 4]);
                af[mt][3] = __float_as_uint(As[r + 8][c + 4]);
            }
            #pragma unroll
            for (int nt = 0; nt < 4; nt++) {
                uint32_t b0 = __float_as_uint(Bs[k8 * 8 + gc][wn * 32 + nt * 8 + gr]);
                uint32_t b1 = __float_as_uint(Bs[k8 * 8 + gc + 4][wn * 32 + nt * 8 + gr]);
                #pragma unroll
                for (int mt = 0; mt < 4; mt++)
                    mma_tf32(acc[mt][nt], af[mt], b0, b1);
            }
        }
        if (k0 < EMBD) {
            __syncthreads();
            #pragma unroll
            for (int rep = 0; rep < 4; rep++) {
                *(float4*)&As[arow + rep * 32][ac] = to_tf32_4(pa[rep]);
                *(float4*)&Bs[brow + rep * 8][bcol] = to_tf32_4(pb[rep]);
            }
            __syncthreads();
        }
    }

    // epilogue: bias add, tf32-round, scatter to Q/K/V
    #pragma unroll
    for (int mt = 0; mt < 4; mt++) {
        #pragma unroll
        for (int half = 0; half < 2; half++) {
            int gi = bm + wm * 64 + mt * 16 + gr + half * 8;
            int b  = gi >> 11;
            int s  = gi & (SEQ - 1);
            #pragma unroll
            for (int nt = 0; nt < 4; nt++) {
                int jc = bn + wn * 32 + nt * 8 + 2 * gc;
                float v0 = acc[mt][nt][half * 2 + 0];
                float v1 = acc[mt][nt][half * 2 + 1];
                if (jc < EMBD) {
                    float2 o = make_float2(to_tf32(v0 + bq[jc]), to_tf32(v1 + bq[jc + 1]));
                    *(float2*)&g_Q[(size_t)gi * EMBD + jc] = o;
                } else if (jc < EMBD + HD) {
                    int d = jc - EMBD;
                    float2 o = make_float2(to_tf32(v0 + bk[d]), to_tf32(v1 + bk[d + 1]));
                    *(float2*)&g_K[((size_t)b * SEQ + s) * HD + d] = o;
                } else {
                    int d = jc - EMBD - HD;
                    float2 o = make_float2(to_tf32(v0 + bv[d]), to_tf32(v1 + bv[d + 1]));
                    *(float2*)&g_V[((size_t)b * SEQ + s) * HD + d] = o;
                }
            }
        }
    }
}

// Output projection: out[8192,1024] = g_A @ Wo + bo, tf32 mma.
__global__ __launch_bounds__(256, 1) void gemm_o_kernel(
    const float* __restrict__ Wo, const float* __restrict__ bo,
    float* __restrict__ out)
{
    __shared__ float As[128][AP];
    __shared__ float Bs[TBK][BP];

    const int tid  = threadIdx.x;
    const int warp = tid >> 5;
    const int lane = tid & 31;
    const int gr   = lane >> 2;
    const int gc   = lane & 3;
    const int wm   = warp >> 2;
    const int wn   = warp & 3;
    const int bm   = blockIdx.y * 128;
    const int bn   = blockIdx.x * 128;

    const int arow = tid >> 3;
    const int ac   = (tid & 7) * 4;
    const int brow = tid >> 5;
    const int bcol = (tid & 31) * 4;

    float acc[4][4][4];
    #pragma unroll
    for (int mt = 0; mt < 4; mt++)
        #pragma unroll
        for (int nt = 0; nt < 4; nt++)
            #pragma unroll
            for (int c = 0; c < 4; c++) acc[mt][nt][c] = 0.0f;

    float4 pa[4], pb[4];
    #pragma unroll
    for (int rep = 0; rep < 4; rep++) {
        pa[rep] = *(const float4*)(g_A + (size_t)(bm + arow + rep * 32) * EMBD + ac);
        pb[rep] = *(const float4*)(Wo + (size_t)(brow + rep * 8) * EMBD + bn + bcol);
    }
    #pragma unroll
    for (int rep = 0; rep < 4; rep++) {
        *(float4*)&As[arow + rep * 32][ac] = to_tf32_4(pa[rep]);
        *(float4*)&Bs[brow + rep * 8][bcol] = to_tf32_4(pb[rep]);
    }
    __syncthreads();

    for (int k0 = TBK; k0 <= EMBD; k0 += TBK) {
        if (k0 < EMBD) {
            #pragma unroll
            for (int rep = 0; rep < 4; rep++) {
                pa[rep] = *(const float4*)(g_A + (size_t)(bm + arow + rep * 32) * EMBD + k0 + ac);
                pb[rep] = *(const float4*)(Wo + (size_t)(k0 + brow + rep * 8) * EMBD + bn + bcol);
            }
        }
        #pragma unroll
        for (int k8 = 0; k8 < 4; k8++) {
            uint32_t af[4][4];
            #pragma unroll
            for (int mt = 0; mt < 4; mt++) {
                int r = wm * 64 + mt * 16 + gr;
                int c = k8 * 8 + gc;
                af[mt][0] = __float_as_uint(As[r][c]);
                af[mt][1] = __float_as_uint(As[r + 8][c]);
                af[mt][2] = __float_as_uint(As[r][c + 4]);
                af[mt][3] = __float_as_uint(As[r + 8][c + 4]);
            }
            #pragma unroll
            for (int nt = 0; nt < 4; nt++) {
                uint32_t b0 = __float_as_uint(Bs[k8 * 8 + gc][wn * 32 + nt * 8 + gr]);
                uint32_t b1 = __float_as_uint(Bs[k8 * 8 + gc + 4][wn * 32 + nt * 8 + gr]);
                #pragma unroll
                for (int mt = 0; mt < 4; mt++)
                    mma_tf32(acc[mt][nt], af[mt], b0, b1);
            }
        }
        if (k0 < EMBD) {
            __syncthreads();
            #pragma unroll
            for (int rep = 0; rep < 4; rep++) {
                *(float4*)&As[arow + rep * 32][ac] = to_tf32_4(pa[rep]);
                *(float4*)&Bs[brow + rep * 8][bcol] = to_tf32_4(pb[rep]);
            }
            __syncthreads();
        }
    }

    #pragma unroll
    for (int mt = 0; mt < 4; mt++) {
        #pragma unroll
        for (int half = 0; half < 2; half++) {
            int gi = bm + wm * 64 + mt * 16 + gr + half * 8;
            #pragma unroll
            for (int nt = 0; nt < 4; nt++) {
                int jc = bn + wn * 32 + nt * 8 + 2 * gc;
                float v0 = acc[mt][nt][half * 2 + 0] + bo[jc];
                float v1 = acc[mt][nt][half * 2 + 1] + bo[jc + 1];
                *(float2*)&out[(size_t)gi * EMBD + jc] = make_float2(v0, v1);
            }
        }
    }
}

// ---------------- flash attention (tf32 mma.sync, online softmax) --------
#define QT 128
#define KT2 64
#define KP 68
#define VP 72
#define PP 68
#define ATTN_SMEM_FLOATS (KT2 * KP + KT2 * VP + QT * PP)
#define ATTN_SMEM_BYTES (ATTN_SMEM_FLOATS * 4)

__global__ __launch_bounds__(256, 1) void attn_kernel()
{
    extern __shared__ float sm[];
    float* Ks = sm;                  // [key][d]
    float* Vs = Ks + KT2 * KP;       // [key][d]
    float* Ps = Vs + KT2 * VP;       // [row][key] ; Q staging before loop

    const int tid  = threadIdx.x;
    const int warp = tid >> 5;
    const int lane = tid & 31;
    const int gr   = lane >> 2;
    const int gc   = lane & 3;
    const int q0 = blockIdx.x * QT;
    const int h  = blockIdx.y;
    const int b  = blockIdx.z;

    const float* Qg = g_Q + ((size_t)(b * SEQ + q0)) * EMBD + h * HD;
    const float* Kg = g_K + (size_t)b * SEQ * HD;
    const float* Vg = g_V + (size_t)b * SEQ * HD;

    #pragma unroll
    for (int rep = 0; rep < 8; rep++) {
        int idx = tid + rep * 256;
        int r   = idx >> 4;
        int c4  = (idx & 15) * 4;
        float4 v = *(const float4*)(Qg + (size_t)r * EMBD + c4);
        v.x *= 0.125f; v.y *= 0.125f; v.z *= 0.125f; v.w *= 0.125f;
        *(float4*)&Ps[r * PP + c4] = v;
    }
    __syncthreads();

    const int r0 = warp * 16 + gr;
    uint32_t qf[8][4];
    #pragma unroll
    for (int k = 0; k < 8; k++) {
        qf[k][0] = __float_as_uint(Ps[r0 * PP + k * 8 + gc]);
        qf[k][1] = __float_as_uint(Ps[(r0 + 8) * PP + k * 8 + gc]);
        qf[k][2] = __float_as_uint(Ps[r0 * PP + k * 8 + gc + 4]);
        qf[k][3] = __float_as_uint(Ps[(r0 + 8) * PP + k * 8 + gc + 4]);
    }

    float oacc[8][4];
    #pragma unroll
    for (int n = 0; n < 8; n++)
        #pragma unroll
        for (int c = 0; c < 4; c++) oacc[n][c] = 0.0f;
    float m0 = -INFINITY, m1 = -INFINITY, l0 = 0.0f, l1 = 0.0f;

    for (int t0 = 0; t0 < SEQ; t0 += KT2) {
        __syncthreads();
        #pragma unroll
        for (int rep = 0; rep < 4; rep++) {
            int idx = tid + rep * 256;
            int r   = idx >> 4;
            int c4  = (idx & 15) * 4;
            float4 kv = *(const float4*)(Kg + (size_t)(t0 + r) * HD + c4);
            *(float4*)&Ks[r * KP + c4] = kv;
            float4 vv = *(const float4*)(Vg + (size_t)(t0 + r) * HD + c4);
            *(float4*)&Vs[r * VP + c4] = vv;
        }
        __syncthreads();

        float sacc[8][4];
        #pragma unroll
        for (int n = 0; n < 8; n++)
            #pragma unroll
            for (int c = 0; c < 4; c++) sacc[n][c] = 0.0f;

        #pragma unroll
        for (int n = 0; n < 8; n++) {
            const float* krow = &Ks[(n * 8 + gr) * KP + gc];
            #pragma unroll
            for (int k = 0; k < 8; k++) {
                uint32_t b0 = __float_as_uint(krow[k * 8]);
                uint32_t b1 = __float_as_uint(krow[k * 8 + 4]);
                mma_tf32(sacc[n], qf[k], b0, b1);
            }
        }

        float rm0 = -INFINITY, rm1 = -INFINITY;
        #pragma unroll
        for (int n = 0; n < 8; n++) {
            rm0 = fmaxf(rm0, fmaxf(sacc[n][0], sacc[n][1]));
            rm1 = fmaxf(rm1, fmaxf(sacc[n][2], sacc[n][3]));
        }
        rm0 = fmaxf(rm0, __shfl_xor_sync(0xffffffffu, rm0, 1));
        rm0 = fmaxf(rm0, __shfl_xor_sync(0xffffffffu, rm0, 2));
        rm1 = fmaxf(rm1, __shfl_xor_sync(0xffffffffu, rm1, 1));
        rm1 = fmaxf(rm1, __shfl_xor_sync(0xffffffffu, rm1, 2));
        float mn0 = fmaxf(m0, rm0), mn1 = fmaxf(m1, rm1);
        float corr0 = fast_exp(m0 - mn0), corr1 = fast_exp(m1 - mn1);
        m0 = mn0; m1 = mn1;

        float ls0 = 0.0f, ls1 = 0.0f;
        #pragma unroll
        for (int n = 0; n < 8; n++) {
            float t00 = trunc_tf32(fast_exp(sacc[n][0] - m0));
            float t01 = trunc_tf32(fast_exp(sacc[n][1] - m0));
            float t10 = trunc_tf32(fast_exp(sacc[n][2] - m1));
            float t11 = trunc_tf32(fast_exp(sacc[n][3] - m1));
            ls0 += t00 + t01;
            ls1 += t10 + t11;
            int col = n * 8 + 2 * gc;
            *(float2*)&Ps[r0 * PP + col]       = make_float2(t00, t01);
            *(float2*)&Ps[(r0 + 8) * PP + col] = make_float2(t10, t11);
        }
        ls0 += __shfl_xor_sync(0xffffffffu, ls0, 1);
        ls0 += __shfl_xor_sync(0xffffffffu, ls0, 2);
        ls1 += __shfl_xor_sync(0xffffffffu, ls1, 1);
        ls1 += __shfl_xor_sync(0xffffffffu, ls1, 2);
        l0 = l0 * corr0 + ls0;
        l1 = l1 * corr1 + ls1;

        #pragma unroll
        for (int n = 0; n < 8; n++) {
            oacc[n][0] *= corr0; oacc[n][1] *= corr0;
            oacc[n][2] *= corr1; oacc[n][3] *= corr1;
        }
        __syncwarp();

        #pragma unroll
        for (int k = 0; k < 8; k++) {
            uint32_t a[4];
            a[0] = __float_as_uint(Ps[r0 * PP + k * 8 + gc]);
            a[1] = __float_as_uint(Ps[(r0 + 8) * PP + k * 8 + gc]);
            a[2] = __float_as_uint(Ps[r0 * PP + k * 8 + gc + 4]);
            a[3] = __float_as_uint(Ps[(r0 + 8) * PP + k * 8 + gc + 4]);
            #pragma unroll
            for (int n = 0; n < 8; n++) {
                uint32_t b0 = __float_as_uint(Vs[(k * 8 + gc) * VP + n * 8 + gr]);
                uint32_t b1 = __float_as_uint(Vs[(k * 8 + gc + 4) * VP + n * 8 + gr]);
                mma_tf32(oacc[n], a, b0, b1);
            }
        }
    }

    float inv0 = 1.0f / l0, inv1 = 1.0f / l1;
    #pragma unroll
    for (int n = 0; n < 8; n++) {
        int col = h * HD + n * 8 + 2 * gc;
        size_t base0 = ((size_t)(b * SEQ + q0 + r0)) * EMBD + col;
        size_t base1 = ((size_t)(b * SEQ + q0 + r0 + 8)) * EMBD + col;
        *(float2*)&g_A[base0] = make_float2(oacc[n][0] * inv0, oacc[n][1] * inv0);
        *(float2*)&g_A[base1] = make_float2(oacc[n][2] * inv1, oacc[n][3] * inv1);
    }
}

// ---------------- launch ----------------
extern "C" void kernel_launch(void* const* d_in, const int* in_sizes, int n_in,
                              void* d_out, int out_size)
{
    const float* x  = (const float*)d_in[0];
    const float* Wq = (const float*)d_in[1];
    const float* bq = (const float*)d_in[2];
    const float* Wk = (const float*)d_in[3];
    const float* bk = (const float*)d_in[4];
    const float* Wv = (const float*)d_in[5];
    const float* bv = (const float*)d_in[6];
    const float* Wo = (const float*)d_in[7];
    const float* bo = (const float*)d_in[8];
    float* out = (float*)d_out;

    cudaFuncSetAttribute(attn_kernel, cudaFuncAttributeMaxDynamicSharedMemorySize,
                         ATTN_SMEM_BYTES);

    gemm_qkv_kernel<<<dim3(NQKV / 128, MTOT / 128), 256>>>(x, Wq, bq, Wk, bk, Wv, bv);
    attn_kernel<<<dim3(SEQ / QT, HEADS, BATCH), 256, ATTN_SMEM_BYTES>>>();
    gemm_o_kernel<<<dim3(EMBD / 128, MTOT / 128), 256>>>(Wo, bo, out);
}